// round 1
// baseline (speedup 1.0000x reference)
#include <cuda_runtime.h>
#include <math.h>

#define M_TOK 16384
#define D_IN  1024
#define D_HID 256
#define N_EXP 64

// Intermediate h = tanh(x@W1+b1), [16384, 256] fp32 (16 MiB device scratch).
__device__ float g_h[M_TOK * D_HID];

// ---------------------------------------------------------------------------
// GEMM1: h = tanh(x[M,1024] @ W1[1024,256] + b1)
// 64x64 block tile, BK=16, 256 threads, 4x4 micro-tile.
// ---------------------------------------------------------------------------
__global__ void __launch_bounds__(256, 4)
gemm1_tanh(const float* __restrict__ x,
           const float* __restrict__ W1,
           const float* __restrict__ b1) {
    __shared__ float As[16][64];   // [k][m] (transposed A tile)
    __shared__ float Bs[16][64];   // [k][n]

    const int tid = threadIdx.x;
    const int tx  = tid & 15;          // 0..15 -> covers 64 cols (4 each)
    const int ty  = tid >> 4;          // 0..15 -> covers 64 rows (4 each)
    const int m0  = blockIdx.y * 64;
    const int n0  = blockIdx.x * 64;

    // A-tile loader: 64 rows x 16 k; one float4 per thread along k
    const int lm  = tid >> 2;          // 0..63 row
    const int lk4 = (tid & 3) * 4;     // 0,4,8,12
    // B-tile loader: 16 k-rows x 64 n; one float4 per thread along n
    const int lkb = tid >> 4;          // 0..15
    const int lnb = (tid & 15) * 4;    // 0..60

    float acc[4][4] = {};

    for (int k0 = 0; k0 < D_IN; k0 += 16) {
        float4 av = *(const float4*)&x[(m0 + lm) * D_IN + k0 + lk4];
        As[lk4 + 0][lm] = av.x;
        As[lk4 + 1][lm] = av.y;
        As[lk4 + 2][lm] = av.z;
        As[lk4 + 3][lm] = av.w;
        *(float4*)&Bs[lkb][lnb] =
            *(const float4*)&W1[(k0 + lkb) * D_HID + n0 + lnb];
        __syncthreads();

        #pragma unroll
        for (int k = 0; k < 16; k++) {
            float4 a = *(const float4*)&As[k][ty * 4];
            float4 b = *(const float4*)&Bs[k][tx * 4];
            float af[4] = {a.x, a.y, a.z, a.w};
            float bf[4] = {b.x, b.y, b.z, b.w};
            #pragma unroll
            for (int i = 0; i < 4; i++) {
                #pragma unroll
                for (int j = 0; j < 4; j++) {
                    acc[i][j] += af[i] * bf[j];
                }
            }
        }
        __syncthreads();
    }

    // Epilogue: +bias, tanh, store
    float bv[4];
    #pragma unroll
    for (int j = 0; j < 4; j++) bv[j] = b1[n0 + tx * 4 + j];

    #pragma unroll
    for (int i = 0; i < 4; i++) {
        const int m = m0 + ty * 4 + i;
        float4 o;
        o.x = tanhf(acc[i][0] + bv[0]);
        o.y = tanhf(acc[i][1] + bv[1]);
        o.z = tanhf(acc[i][2] + bv[2]);
        o.w = tanhf(acc[i][3] + bv[3]);
        *(float4*)&g_h[m * D_HID + n0 + tx * 4] = o;
    }
}

// ---------------------------------------------------------------------------
// GEMM2 + top-2 + softmax + scatter:
//   logits = h[M,256] @ W2[256,64] + b2
//   gates  = scatter(softmax(top2(logits)))
// 64-token block covers full N=64. Epilogue does per-token top-2.
// Output layout: d_out[0 : M*64)      = gates
//                d_out[M*64 : 2*M*64) = gate_logits
// ---------------------------------------------------------------------------
__global__ void __launch_bounds__(256, 2)
gemm2_topk(const float* __restrict__ W2,
           const float* __restrict__ b2,
           float* __restrict__ out) {
    __shared__ float As[16][64];     // [k][m]
    __shared__ float Bs[16][64];     // [k][e]
    __shared__ float Ls[64][65];     // logits tile, stride 65 -> conflict-free scan
    __shared__ float sg1[64], sg2[64];
    __shared__ int   si1[64], si2[64];

    const int tid = threadIdx.x;
    const int tx  = tid & 15;
    const int ty  = tid >> 4;
    const int m0  = blockIdx.x * 64;

    const int lm  = tid >> 2;
    const int lk4 = (tid & 3) * 4;
    const int lkb = tid >> 4;
    const int lnb = (tid & 15) * 4;

    float acc[4][4] = {};

    for (int k0 = 0; k0 < D_HID; k0 += 16) {
        float4 av = *(const float4*)&g_h[(m0 + lm) * D_HID + k0 + lk4];
        As[lk4 + 0][lm] = av.x;
        As[lk4 + 1][lm] = av.y;
        As[lk4 + 2][lm] = av.z;
        As[lk4 + 3][lm] = av.w;
        *(float4*)&Bs[lkb][lnb] =
            *(const float4*)&W2[(k0 + lkb) * N_EXP + lnb];
        __syncthreads();

        #pragma unroll
        for (int k = 0; k < 16; k++) {
            float4 a = *(const float4*)&As[k][ty * 4];
            float4 b = *(const float4*)&Bs[k][tx * 4];
            float af[4] = {a.x, a.y, a.z, a.w};
            float bf[4] = {b.x, b.y, b.z, b.w};
            #pragma unroll
            for (int i = 0; i < 4; i++) {
                #pragma unroll
                for (int j = 0; j < 4; j++) {
                    acc[i][j] += af[i] * bf[j];
                }
            }
        }
        __syncthreads();
    }

    // Add bias, write logits to gmem and to smem tile
    float* out_logits = out + (size_t)M_TOK * N_EXP;
    float bv[4];
    #pragma unroll
    for (int j = 0; j < 4; j++) bv[j] = b2[tx * 4 + j];

    #pragma unroll
    for (int i = 0; i < 4; i++) {
        const int r = ty * 4 + i;
        const int m = m0 + r;
        float4 o;
        o.x = acc[i][0] + bv[0];
        o.y = acc[i][1] + bv[1];
        o.z = acc[i][2] + bv[2];
        o.w = acc[i][3] + bv[3];
        Ls[r][tx * 4 + 0] = o.x;
        Ls[r][tx * 4 + 1] = o.y;
        Ls[r][tx * 4 + 2] = o.z;
        Ls[r][tx * 4 + 3] = o.w;
        *(float4*)&out_logits[m * N_EXP + tx * 4] = o;
    }
    __syncthreads();

    // Per-token top-2 (jax.lax.top_k tie-break: lower index wins -> strict >)
    if (tid < 64) {
        const int t = tid;
        float v1 = -1e30f, v2 = -1e30f;
        int   i1 = 0,      i2 = 0;
        #pragma unroll 8
        for (int e = 0; e < N_EXP; e++) {
            float v = Ls[t][e];
            if (v > v1) { v2 = v1; i2 = i1; v1 = v; i1 = e; }
            else if (v > v2) { v2 = v; i2 = e; }
        }
        // softmax over {v1, v2} (v1 is the max)
        float e2 = expf(v2 - v1);
        float inv = 1.0f / (1.0f + e2);
        sg1[t] = inv;
        sg2[t] = e2 * inv;
        si1[t] = i1;
        si2[t] = i2;
    }
    __syncthreads();

    // Scatter gates (dense write: zeros everywhere except the two winners)
    #pragma unroll
    for (int i = 0; i < 4; i++) {
        const int r = ty * 4 + i;
        const int m = m0 + r;
        const int i1 = si1[r], i2 = si2[r];
        const float g1 = sg1[r], g2 = sg2[r];
        float4 o;
        float v[4];
        #pragma unroll
        for (int j = 0; j < 4; j++) {
            const int e = tx * 4 + j;
            v[j] = (e == i1) ? g1 : ((e == i2) ? g2 : 0.0f);
        }
        o.x = v[0]; o.y = v[1]; o.z = v[2]; o.w = v[3];
        *(float4*)&out[m * N_EXP + tx * 4] = o;
    }
}

// ---------------------------------------------------------------------------
extern "C" void kernel_launch(void* const* d_in, const int* in_sizes, int n_in,
                              void* d_out, int out_size) {
    const float* x  = (const float*)d_in[0];
    const float* W1 = (const float*)d_in[1];
    const float* b1 = (const float*)d_in[2];
    const float* W2 = (const float*)d_in[3];
    const float* b2 = (const float*)d_in[4];
    float* out = (float*)d_out;

    dim3 grid1(D_HID / 64, M_TOK / 64);   // (4, 256)
    gemm1_tanh<<<grid1, 256>>>(x, W1, b1);

    gemm2_topk<<<M_TOK / 64, 256>>>(W2, b2, out);
}

// round 3
// speedup vs baseline: 1.3820x; 1.3820x over previous
#include <cuda_runtime.h>
#include <math.h>
#include <stdint.h>

#define M_TOK 16384
#define D_IN  1024
#define D_HID 256
#define N_EXP 64
#define PITCH 36            // KC + 4 pad, bank-conflict-free fragment loads

// Scratch (device globals: no allocs allowed)
__device__ float g_h[M_TOK * D_HID];          // tanh(x@W1+b1), fp32
__device__ float g_w1t_hi[D_HID * D_IN];      // W1^T, tf32-hi  [256,1024]
__device__ float g_w1t_lo[D_HID * D_IN];      // W1^T, tf32(residual)

// ---------------------------------------------------------------------------
__device__ __forceinline__ uint32_t smem_u32(const void* p) {
    uint32_t a;
    asm("{ .reg .u64 t; cvta.to.shared.u64 t, %1; cvt.u32.u64 %0, t; }"
        : "=r"(a) : "l"(p));
    return a;
}
__device__ __forceinline__ float to_tf32(float x) {
    float r;
    asm("cvt.rna.tf32.f32 %0, %1;" : "=f"(r) : "f"(x));
    return r;
}
__device__ __forceinline__ void cp16(uint32_t dst, const void* src) {
    asm volatile("cp.async.cg.shared.global [%0], [%1], 16;"
                 :: "r"(dst), "l"(src));
}
__device__ __forceinline__ void mma_tf32(float* c, const uint32_t* a,
                                         const uint32_t* b) {
    asm volatile(
        "mma.sync.aligned.m16n8k8.row.col.f32.tf32.tf32.f32 "
        "{%0,%1,%2,%3}, {%4,%5,%6,%7}, {%8,%9}, {%0,%1,%2,%3};"
        : "+f"(c[0]), "+f"(c[1]), "+f"(c[2]), "+f"(c[3])
        : "r"(a[0]), "r"(a[1]), "r"(a[2]), "r"(a[3]), "r"(b[0]), "r"(b[1]));
}

// ---------------------------------------------------------------------------
// Prep: W1 [1024,256] -> W1T hi/lo [256,1024] (transpose + tf32 split)
// ---------------------------------------------------------------------------
__global__ void __launch_bounds__(256)
prep_w1(const float* __restrict__ W1) {
    __shared__ float t[32][33];
    const int n0 = blockIdx.x * 32;
    const int k0 = blockIdx.y * 32;
    const int tx = threadIdx.x & 31;
    const int ty = threadIdx.x >> 5;
    #pragma unroll
    for (int i = 0; i < 32; i += 8)
        t[ty + i][tx] = W1[(k0 + ty + i) * D_HID + n0 + tx];
    __syncthreads();
    #pragma unroll
    for (int i = 0; i < 32; i += 8) {
        float v  = t[tx][ty + i];
        float hi = to_tf32(v);
        g_w1t_hi[(n0 + ty + i) * D_IN + k0 + tx] = hi;
        g_w1t_lo[(n0 + ty + i) * D_IN + k0 + tx] = to_tf32(v - hi);
    }
}

// ---------------------------------------------------------------------------
// GEMM1 (mma.sync 3xTF32): h = tanh(x[16384,1024] @ W1[1024,256] + b1)
// Block 128x128, 8 warps (warp tile 32x64), KC=32.
// Smem (floats): AsH 0, AsL 4608, BsH[2] 9216/18432, BsL[2] 13824/23040
// ---------------------------------------------------------------------------
#define SMEM_FLOATS 27648
#define SMEM_BYTES  (SMEM_FLOATS * 4)

__global__ void __launch_bounds__(256)
gemm1_mma(const float* __restrict__ x, const float* __restrict__ b1) {
    extern __shared__ float sm[];
    float* const AsH = sm;
    float* const AsL = sm + 4608;
    float* const BH0 = sm + 9216;
    float* const BL0 = sm + 13824;
    float* const BH1 = sm + 18432;
    float* const BL1 = sm + 23040;

    const int tid  = threadIdx.x;
    const int lane = tid & 31;
    const int w    = tid >> 5;
    const int wm   = (w & 3) * 32;
    const int wn   = (w >> 2) * 64;
    const int m0   = blockIdx.y * 128;
    const int n0   = blockIdx.x * 128;

    const uint32_t sb = smem_u32(sm);
    const uint32_t uBH[2] = {sb + 9216u * 4, sb + 18432u * 4};
    const uint32_t uBL[2] = {sb + 13824u * 4, sb + 23040u * 4};

    // loader mapping: idx = tid + 256*r -> row = idx>>3 (0..127), g = idx&7
    const int lrow = tid >> 3;          // base row for r=0 pattern is idx>>3;
    const int lg   = tid & 7;           // recomputed per r below

    float c[2][8][4] = {};
    float4 xv[4];

    // ---- prologue: B0 via cp.async, x0 into regs
    {
        #pragma unroll
        for (int r = 0; r < 4; r++) {
            int idx = tid + 256 * r;
            int row = idx >> 3, g = idx & 7;
            uint32_t off = (uint32_t)(row * PITCH + g * 4) * 4;
            cp16(uBH[0] + off, &g_w1t_hi[(size_t)(n0 + row) * D_IN + g * 4]);
            cp16(uBL[0] + off, &g_w1t_lo[(size_t)(n0 + row) * D_IN + g * 4]);
        }
        asm volatile("cp.async.commit_group;" ::: "memory");
        #pragma unroll
        for (int r = 0; r < 4; r++) {
            int idx = tid + 256 * r;
            int row = idx >> 3, g = idx & 7;
            xv[r] = *(const float4*)&x[(size_t)(m0 + row) * D_IN + g * 4];
        }
    }

    for (int kb = 0; kb < D_IN / 32; kb++) {
        const int buf = kb & 1;
        float* const cBH = buf ? BH1 : BH0;
        float* const cBL = buf ? BL1 : BL0;

        // split current x regs -> As
        #pragma unroll
        for (int r = 0; r < 4; r++) {
            int idx = tid + 256 * r;
            int row = idx >> 3, g = idx & 7;
            float4 v = xv[r], h4, l4;
            h4.x = to_tf32(v.x); l4.x = to_tf32(v.x - h4.x);
            h4.y = to_tf32(v.y); l4.y = to_tf32(v.y - h4.y);
            h4.z = to_tf32(v.z); l4.z = to_tf32(v.z - h4.z);
            h4.w = to_tf32(v.w); l4.w = to_tf32(v.w - h4.w);
            *(float4*)&AsH[row * PITCH + g * 4] = h4;
            *(float4*)&AsL[row * PITCH + g * 4] = l4;
        }

        // prefetch next B (cp.async) and next x (regs)
        if (kb < D_IN / 32 - 1) {
            const int nk = (kb + 1) * 32;
            #pragma unroll
            for (int r = 0; r < 4; r++) {
                int idx = tid + 256 * r;
                int row = idx >> 3, g = idx & 7;
                uint32_t off = (uint32_t)(row * PITCH + g * 4) * 4;
                cp16(uBH[buf ^ 1] + off,
                     &g_w1t_hi[(size_t)(n0 + row) * D_IN + nk + g * 4]);
                cp16(uBL[buf ^ 1] + off,
                     &g_w1t_lo[(size_t)(n0 + row) * D_IN + nk + g * 4]);
            }
            asm volatile("cp.async.commit_group;" ::: "memory");
            #pragma unroll
            for (int r = 0; r < 4; r++) {
                int idx = tid + 256 * r;
                int row = idx >> 3, g = idx & 7;
                xv[r] = *(const float4*)&x[(size_t)(m0 + row) * D_IN + nk + g * 4];
            }
            asm volatile("cp.async.wait_group 1;" ::: "memory");
        } else {
            asm volatile("cp.async.wait_group 0;" ::: "memory");
        }
        __syncthreads();

        // ---- compute over (AsH/AsL, cBH/cBL)
        #pragma unroll
        for (int kk = 0; kk < 32; kk += 8) {
            const int k = kk + (lane & 3);
            uint32_t Ah[2][4], Al[2][4];
            #pragma unroll
            for (int mt = 0; mt < 2; mt++) {
                const int m = wm + mt * 16 + (lane >> 2);
                Ah[mt][0] = __float_as_uint(AsH[m * PITCH + k]);
                Ah[mt][1] = __float_as_uint(AsH[(m + 8) * PITCH + k]);
                Ah[mt][2] = __float_as_uint(AsH[m * PITCH + k + 4]);
                Ah[mt][3] = __float_as_uint(AsH[(m + 8) * PITCH + k + 4]);
                Al[mt][0] = __float_as_uint(AsL[m * PITCH + k]);
                Al[mt][1] = __float_as_uint(AsL[(m + 8) * PITCH + k]);
                Al[mt][2] = __float_as_uint(AsL[m * PITCH + k + 4]);
                Al[mt][3] = __float_as_uint(AsL[(m + 8) * PITCH + k + 4]);
            }
            #pragma unroll
            for (int nt = 0; nt < 8; nt++) {
                const int n = wn + nt * 8 + (lane >> 2);
                uint32_t bh[2], bl[2];
                bh[0] = __float_as_uint(cBH[n * PITCH + k]);
                bh[1] = __float_as_uint(cBH[n * PITCH + k + 4]);
                bl[0] = __float_as_uint(cBL[n * PITCH + k]);
                bl[1] = __float_as_uint(cBL[n * PITCH + k + 4]);
                #pragma unroll
                for (int mt = 0; mt < 2; mt++) {
                    mma_tf32(c[mt][nt], Ah[mt], bh);
                    mma_tf32(c[mt][nt], Ah[mt], bl);
                    mma_tf32(c[mt][nt], Al[mt], bh);
                }
            }
        }
        __syncthreads();
    }

    // ---- epilogue: tanh(c + b1) -> g_h
    #pragma unroll
    for (int mt = 0; mt < 2; mt++) {
        const int m = m0 + wm + mt * 16 + (lane >> 2);
        #pragma unroll
        for (int nt = 0; nt < 8; nt++) {
            const int n = n0 + wn + nt * 8 + (lane & 3) * 2;
            const float bn0 = __ldg(&b1[n]);
            const float bn1 = __ldg(&b1[n + 1]);
            float2 o0, o1;
            o0.x = tanhf(c[mt][nt][0] + bn0);
            o0.y = tanhf(c[mt][nt][1] + bn1);
            o1.x = tanhf(c[mt][nt][2] + bn0);
            o1.y = tanhf(c[mt][nt][3] + bn1);
            *(float2*)&g_h[(size_t)m * D_HID + n]       = o0;
            *(float2*)&g_h[(size_t)(m + 8) * D_HID + n] = o1;
        }
    }
}

// ---------------------------------------------------------------------------
// GEMM2 + top-2 + softmax + scatter (R0 version: 27.7 us)
// ---------------------------------------------------------------------------
__global__ void __launch_bounds__(256, 2)
gemm2_topk(const float* __restrict__ W2,
           const float* __restrict__ b2,
           float* __restrict__ out) {
    __shared__ float As[16][64];
    __shared__ float Bs[16][64];
    __shared__ float Ls[64][65];
    __shared__ float sg1[64], sg2[64];
    __shared__ int   si1[64], si2[64];

    const int tid = threadIdx.x;
    const int tx  = tid & 15;
    const int ty  = tid >> 4;
    const int m0  = blockIdx.x * 64;

    const int lm  = tid >> 2;
    const int lk4 = (tid & 3) * 4;
    const int lkb = tid >> 4;
    const int lnb = (tid & 15) * 4;

    float acc[4][4] = {};

    for (int k0 = 0; k0 < D_HID; k0 += 16) {
        float4 av = *(const float4*)&g_h[(size_t)(m0 + lm) * D_HID + k0 + lk4];
        As[lk4 + 0][lm] = av.x;
        As[lk4 + 1][lm] = av.y;
        As[lk4 + 2][lm] = av.z;
        As[lk4 + 3][lm] = av.w;
        *(float4*)&Bs[lkb][lnb] =
            *(const float4*)&W2[(k0 + lkb) * N_EXP + lnb];
        __syncthreads();

        #pragma unroll
        for (int k = 0; k < 16; k++) {
            float4 a = *(const float4*)&As[k][ty * 4];
            float4 b = *(const float4*)&Bs[k][tx * 4];
            float af[4] = {a.x, a.y, a.z, a.w};
            float bf[4] = {b.x, b.y, b.z, b.w};
            #pragma unroll
            for (int i = 0; i < 4; i++)
                #pragma unroll
                for (int j = 0; j < 4; j++)
                    acc[i][j] += af[i] * bf[j];
        }
        __syncthreads();
    }

    float* out_logits = out + (size_t)M_TOK * N_EXP;
    float bv[4];
    #pragma unroll
    for (int j = 0; j < 4; j++) bv[j] = b2[tx * 4 + j];

    #pragma unroll
    for (int i = 0; i < 4; i++) {
        const int r = ty * 4 + i;
        const int m = m0 + r;
        float4 o;
        o.x = acc[i][0] + bv[0];
        o.y = acc[i][1] + bv[1];
        o.z = acc[i][2] + bv[2];
        o.w = acc[i][3] + bv[3];
        Ls[r][tx * 4 + 0] = o.x;
        Ls[r][tx * 4 + 1] = o.y;
        Ls[r][tx * 4 + 2] = o.z;
        Ls[r][tx * 4 + 3] = o.w;
        *(float4*)&out_logits[(size_t)m * N_EXP + tx * 4] = o;
    }
    __syncthreads();

    if (tid < 64) {
        const int t = tid;
        float v1 = -1e30f, v2 = -1e30f;
        int   i1 = 0,      i2 = 0;
        #pragma unroll 8
        for (int e = 0; e < N_EXP; e++) {
            float v = Ls[t][e];
            if (v > v1) { v2 = v1; i2 = i1; v1 = v; i1 = e; }
            else if (v > v2) { v2 = v; i2 = e; }
        }
        float e2 = expf(v2 - v1);
        float inv = 1.0f / (1.0f + e2);
        sg1[t] = inv;
        sg2[t] = e2 * inv;
        si1[t] = i1;
        si2[t] = i2;
    }
    __syncthreads();

    #pragma unroll
    for (int i = 0; i < 4; i++) {
        const int r = ty * 4 + i;
        const int m = m0 + r;
        const int i1 = si1[r], i2 = si2[r];
        const float g1 = sg1[r], g2 = sg2[r];
        float4 o;
        float v[4];
        #pragma unroll
        for (int j = 0; j < 4; j++) {
            const int e = tx * 4 + j;
            v[j] = (e == i1) ? g1 : ((e == i2) ? g2 : 0.0f);
        }
        o.x = v[0]; o.y = v[1]; o.z = v[2]; o.w = v[3];
        *(float4*)&out[(size_t)m * N_EXP + tx * 4] = o;
    }
}

// ---------------------------------------------------------------------------
extern "C" void kernel_launch(void* const* d_in, const int* in_sizes, int n_in,
                              void* d_out, int out_size) {
    const float* x  = (const float*)d_in[0];
    const float* W1 = (const float*)d_in[1];
    const float* b1 = (const float*)d_in[2];
    const float* W2 = (const float*)d_in[3];
    const float* b2 = (const float*)d_in[4];
    float* out = (float*)d_out;

    static int smem_set = 0;
    if (!smem_set) {
        cudaFuncSetAttribute(gemm1_mma,
                             cudaFuncAttributeMaxDynamicSharedMemorySize,
                             SMEM_BYTES);
        smem_set = 1;
    }

    prep_w1<<<dim3(8, 32), 256>>>(W1);
    gemm1_mma<<<dim3(2, 128), 256, SMEM_BYTES>>>(x, b1);
    gemm2_topk<<<M_TOK / 64, 256>>>(W2, b2, out);
}

// round 5
// speedup vs baseline: 1.9578x; 1.4166x over previous
#include <cuda_runtime.h>
#include <cuda_fp16.h>
#include <math.h>
#include <stdint.h>

#define M_TOK 16384
#define D_IN  1024
#define D_HID 256
#define N_EXP 64

// Packed hi/lo fp16 splits: uint2 = {half2(hi0,hi1), half2(lo0,lo1)} per k-pair
__device__ uint2 g_hp[M_TOK * (D_HID / 2)];   // h packed   [16384][128]
__device__ uint2 g_w1p[D_HID * (D_IN / 2)];   // W1^T packed [256][512]
__device__ uint2 g_w2p[N_EXP * (D_HID / 2)];  // W2^T packed [64][128]

// ---------------------------------------------------------------------------
__device__ __forceinline__ uint32_t smem_u32(const void* p) {
    uint32_t a;
    asm("{ .reg .u64 t; cvta.to.shared.u64 t, %1; cvt.u32.u64 %0, t; }"
        : "=r"(a) : "l"(p));
    return a;
}
__device__ __forceinline__ void cp16(uint32_t dst, const void* src) {
    asm volatile("cp.async.cg.shared.global [%0], [%1], 16;"
                 :: "r"(dst), "l"(src));
}
__device__ __forceinline__ uint32_t pack_h2(float a, float b) {
    __half2 h = __floats2half2_rn(a, b);
    return *(uint32_t*)&h;
}
// split (v0,v1) -> {hi half2, lo half2}
__device__ __forceinline__ uint2 split2(float v0, float v1) {
    float h0 = __half2float(__float2half_rn(v0));
    float h1 = __half2float(__float2half_rn(v1));
    uint2 u;
    u.x = pack_h2(h0, h1);
    u.y = pack_h2(v0 - h0, v1 - h1);
    return u;
}
__device__ __forceinline__ void mma_f16(float* c, uint32_t a0, uint32_t a1,
                                        uint32_t a2, uint32_t a3,
                                        uint32_t b0, uint32_t b1) {
    asm volatile(
        "mma.sync.aligned.m16n8k16.row.col.f32.f16.f16.f32 "
        "{%0,%1,%2,%3}, {%4,%5,%6,%7}, {%8,%9}, {%0,%1,%2,%3};"
        : "+f"(c[0]), "+f"(c[1]), "+f"(c[2]), "+f"(c[3])
        : "r"(a0), "r"(a1), "r"(a2), "r"(a3), "r"(b0), "r"(b1));
}

// ---------------------------------------------------------------------------
// Prep: transpose + fp16 hi/lo split + pack for W1 (z=0) and W2 (z=1)
// ---------------------------------------------------------------------------
__global__ void __launch_bounds__(256)
prep_w(const float* __restrict__ W1, const float* __restrict__ W2) {
    __shared__ float t[32][33];
    const int z = blockIdx.z;
    if (z == 1 && (blockIdx.x >= 2 || blockIdx.y >= 8)) return;

    const int n0 = blockIdx.x * 32;
    const int k0 = blockIdx.y * 32;
    const int tx = threadIdx.x & 31;
    const int ty = threadIdx.x >> 5;
    const float* W  = z ? W2 : W1;
    const int   ncols = z ? N_EXP : D_HID;

    #pragma unroll
    for (int i = 0; i < 32; i += 8)
        t[ty + i][tx] = W[(k0 + ty + i) * ncols + n0 + tx];
    __syncthreads();

    const int nn = threadIdx.x >> 3;       // 0..31
    const int jj = threadIdx.x & 7;        // 0..7 -> 2 pairs each
    uint2* dst   = z ? g_w2p : g_w1p;
    const int kp_pitch = z ? (D_HID / 2) : (D_IN / 2);
    #pragma unroll
    for (int q = 0; q < 2; q++) {
        const int p = jj * 2 + q;          // local kpair 0..15
        float v0 = t[2 * p][nn];
        float v1 = t[2 * p + 1][nn];
        dst[(size_t)(n0 + nn) * kp_pitch + k0 / 2 + p] = split2(v0, v1);
    }
}

// ---------------------------------------------------------------------------
// GEMM1 (fp16x3 mma): h = tanh(x[16384,1024] @ W1[1024,256] + b1)
// Block 128x128, 8 warps (warp 32x64), KC=32 (16 kpairs). Pitch 20 uint2.
// Smem (uint2): A [0,2560)  B0 [2560,5120)  B1 [5120,7680)  -> 61440 B
// ---------------------------------------------------------------------------
#define G1_PITCH 20
#define G1_SMEM  (7680 * 8)

__global__ void __launch_bounds__(256)
gemm1_mma(const float* __restrict__ x, const float* __restrict__ b1) {
    extern __shared__ uint2 sm[];
    uint2* const As = sm;
    uint2* const Bs[2] = {sm + 2560, sm + 5120};

    const int tid  = threadIdx.x;
    const int lane = tid & 31;
    const int grp  = lane >> 2;
    const int kq   = lane & 3;
    const int w    = tid >> 5;
    const int wm   = (w & 3) * 32;
    const int wn   = (w >> 2) * 64;
    const int m0   = blockIdx.y * 128;
    const int n0   = blockIdx.x * 128;

    const uint32_t uB[2] = {smem_u32(Bs[0]), smem_u32(Bs[1])};

    float c[2][8][4] = {};
    float4 xv[4];

    // prologue: B(kb=0) via cp.async, x(kb=0) into regs
    #pragma unroll
    for (int r = 0; r < 4; r++) {
        int idx = tid + 256 * r;
        int row = idx >> 3, g = idx & 7;
        cp16(uB[0] + (uint32_t)(row * G1_PITCH + g * 2) * 8,
             &g_w1p[(size_t)(n0 + row) * 512 + g * 2]);
        xv[r] = *(const float4*)&x[(size_t)(m0 + row) * D_IN + g * 4];
    }
    asm volatile("cp.async.commit_group;" ::: "memory");

    for (int kb = 0; kb < D_IN / 32; kb++) {
        const int buf = kb & 1;

        // split x regs -> As (interleaved hi/lo, one 16B store per float4)
        #pragma unroll
        for (int r = 0; r < 4; r++) {
            int idx = tid + 256 * r;
            int row = idx >> 3, g = idx & 7;
            uint2 p0 = split2(xv[r].x, xv[r].y);
            uint2 p1 = split2(xv[r].z, xv[r].w);
            uint4 st = make_uint4(p0.x, p0.y, p1.x, p1.y);
            *(uint4*)&As[row * G1_PITCH + g * 2] = st;
        }

        if (kb < D_IN / 32 - 1) {
            const int nk = (kb + 1) * 32;
            #pragma unroll
            for (int r = 0; r < 4; r++) {
                int idx = tid + 256 * r;
                int row = idx >> 3, g = idx & 7;
                cp16(uB[buf ^ 1] + (uint32_t)(row * G1_PITCH + g * 2) * 8,
                     &g_w1p[(size_t)(n0 + row) * 512 + nk / 2 + g * 2]);
                xv[r] = *(const float4*)&x[(size_t)(m0 + row) * D_IN + nk + g * 4];
            }
            asm volatile("cp.async.commit_group;" ::: "memory");
            asm volatile("cp.async.wait_group 1;" ::: "memory");
        } else {
            asm volatile("cp.async.wait_group 0;" ::: "memory");
        }
        __syncthreads();

        const uint2* const cB = Bs[buf];
        #pragma unroll
        for (int s = 0; s < 2; s++) {           // two k16 steps per KC=32
            const int kb8 = s * 8;
            uint2 Af[2][4];
            #pragma unroll
            for (int mt = 0; mt < 2; mt++) {
                const int mr = wm + mt * 16 + grp;
                Af[mt][0] = As[mr * G1_PITCH + kb8 + kq];
                Af[mt][1] = As[(mr + 8) * G1_PITCH + kb8 + kq];
                Af[mt][2] = As[mr * G1_PITCH + kb8 + 4 + kq];
                Af[mt][3] = As[(mr + 8) * G1_PITCH + kb8 + 4 + kq];
            }
            #pragma unroll
            for (int nt = 0; nt < 8; nt++) {
                const int n = wn + nt * 8 + grp;
                uint2 b0 = cB[n * G1_PITCH + kb8 + kq];
                uint2 b1 = cB[n * G1_PITCH + kb8 + 4 + kq];
                #pragma unroll
                for (int mt = 0; mt < 2; mt++) {
                    mma_f16(c[mt][nt], Af[mt][0].x, Af[mt][1].x,
                            Af[mt][2].x, Af[mt][3].x, b0.x, b1.x);   // hi*hi
                    mma_f16(c[mt][nt], Af[mt][0].x, Af[mt][1].x,
                            Af[mt][2].x, Af[mt][3].x, b0.y, b1.y);   // hi*lo
                    mma_f16(c[mt][nt], Af[mt][0].y, Af[mt][1].y,
                            Af[mt][2].y, Af[mt][3].y, b0.x, b1.x);   // lo*hi
                }
            }
        }
        __syncthreads();
    }

    // epilogue: tanh(c + b1) -> packed hi/lo fp16 in g_hp
    #pragma unroll
    for (int mt = 0; mt < 2; mt++) {
        const int m = m0 + wm + mt * 16 + grp;
        #pragma unroll
        for (int nt = 0; nt < 8; nt++) {
            const int n = n0 + wn + nt * 8 + kq * 2;
            const float bn0 = __ldg(&b1[n]);
            const float bn1 = __ldg(&b1[n + 1]);
            float t0 = tanhf(c[mt][nt][0] + bn0);
            float t1 = tanhf(c[mt][nt][1] + bn1);
            float t2 = tanhf(c[mt][nt][2] + bn0);
            float t3 = tanhf(c[mt][nt][3] + bn1);
            g_hp[(size_t)m * 128 + (n >> 1)]       = split2(t0, t1);
            g_hp[(size_t)(m + 8) * 128 + (n >> 1)] = split2(t2, t3);
        }
    }
}

// ---------------------------------------------------------------------------
// GEMM2 (fp16x3 mma) + top-2 + softmax + scatter.
// Block: 128 tokens x 64 experts, K=256 (KC=64 -> 4 chunks), 8 warps (32x32).
// Smem bytes: A0 0 (36864) A1 36864 B0 73728 (18432) B1 92160
//             Ls 110592 (128x65 f) sg1 143872 sg2 144384 si1 144896 si2 145408
// ---------------------------------------------------------------------------
#define G2_PITCH 36
#define G2_SMEM  145920

__global__ void __launch_bounds__(256)
gemm2_mma(const float* __restrict__ b2, float* __restrict__ out) {
    extern __shared__ char smc[];
    uint2* const A[2]  = {(uint2*)smc, (uint2*)(smc + 36864)};
    uint2* const B[2]  = {(uint2*)(smc + 73728), (uint2*)(smc + 92160)};
    float* const Ls    = (float*)(smc + 110592);
    float* const sg1   = (float*)(smc + 143872);
    float* const sg2   = (float*)(smc + 144384);
    int*   const si1   = (int*)(smc + 144896);
    int*   const si2   = (int*)(smc + 145408);

    const int tid  = threadIdx.x;
    const int lane = tid & 31;
    const int grp  = lane >> 2;
    const int kq   = lane & 3;
    const int w    = tid >> 5;
    const int wm   = (w & 3) * 32;
    const int wn   = (w >> 2) * 32;
    const int m0   = blockIdx.x * 128;

    const uint32_t uA[2] = {smem_u32(A[0]), smem_u32(A[1])};
    const uint32_t uB[2] = {smem_u32(B[0]), smem_u32(B[1])};

    float c[2][4][4] = {};

    // prologue: chunk 0
    #pragma unroll
    for (int r = 0; r < 8; r++) {
        int idx = tid + 256 * r;
        int row = idx >> 4, g = idx & 15;
        cp16(uA[0] + (uint32_t)(row * G2_PITCH + g * 2) * 8,
             &g_hp[(size_t)(m0 + row) * 128 + g * 2]);
    }
    #pragma unroll
    for (int r = 0; r < 4; r++) {
        int idx = tid + 256 * r;
        int row = idx >> 4, g = idx & 15;
        cp16(uB[0] + (uint32_t)(row * G2_PITCH + g * 2) * 8,
             &g_w2p[(size_t)row * 128 + g * 2]);
    }
    asm volatile("cp.async.commit_group;" ::: "memory");

    for (int kb = 0; kb < 4; kb++) {
        const int buf = kb & 1;
        if (kb < 3) {
            const int nkp = (kb + 1) * 32;
            #pragma unroll
            for (int r = 0; r < 8; r++) {
                int idx = tid + 256 * r;
                int row = idx >> 4, g = idx & 15;
                cp16(uA[buf ^ 1] + (uint32_t)(row * G2_PITCH + g * 2) * 8,
                     &g_hp[(size_t)(m0 + row) * 128 + nkp + g * 2]);
            }
            #pragma unroll
            for (int r = 0; r < 4; r++) {
                int idx = tid + 256 * r;
                int row = idx >> 4, g = idx & 15;
                cp16(uB[buf ^ 1] + (uint32_t)(row * G2_PITCH + g * 2) * 8,
                     &g_w2p[(size_t)row * 128 + nkp + g * 2]);
            }
            asm volatile("cp.async.commit_group;" ::: "memory");
            asm volatile("cp.async.wait_group 1;" ::: "memory");
        } else {
            asm volatile("cp.async.wait_group 0;" ::: "memory");
        }
        __syncthreads();

        const uint2* const cA = A[buf];
        const uint2* const cB = B[buf];
        #pragma unroll
        for (int s = 0; s < 4; s++) {          // four k16 steps per KC=64
            const int kb8 = s * 8;
            uint2 Af[2][4];
            #pragma unroll
            for (int mt = 0; mt < 2; mt++) {
                const int mr = wm + mt * 16 + grp;
                Af[mt][0] = cA[mr * G2_PITCH + kb8 + kq];
                Af[mt][1] = cA[(mr + 8) * G2_PITCH + kb8 + kq];
                Af[mt][2] = cA[mr * G2_PITCH + kb8 + 4 + kq];
                Af[mt][3] = cA[(mr + 8) * G2_PITCH + kb8 + 4 + kq];
            }
            #pragma unroll
            for (int nt = 0; nt < 4; nt++) {
                const int n = wn + nt * 8 + grp;
                uint2 b0 = cB[n * G2_PITCH + kb8 + kq];
                uint2 b1 = cB[n * G2_PITCH + kb8 + 4 + kq];
                #pragma unroll
                for (int mt = 0; mt < 2; mt++) {
                    mma_f16(c[mt][nt], Af[mt][0].x, Af[mt][1].x,
                            Af[mt][2].x, Af[mt][3].x, b0.x, b1.x);
                    mma_f16(c[mt][nt], Af[mt][0].x, Af[mt][1].x,
                            Af[mt][2].x, Af[mt][3].x, b0.y, b1.y);
                    mma_f16(c[mt][nt], Af[mt][0].y, Af[mt][1].y,
                            Af[mt][2].y, Af[mt][3].y, b0.x, b1.x);
                }
            }
        }
        __syncthreads();
    }

    // epilogue: logits -> gmem + smem
    float* out_logits = out + (size_t)M_TOK * N_EXP;
    #pragma unroll
    for (int mt = 0; mt < 2; mt++) {
        const int ml = wm + mt * 16 + grp;
        const int m  = m0 + ml;
        #pragma unroll
        for (int nt = 0; nt < 4; nt++) {
            const int n = wn + nt * 8 + kq * 2;
            const float bn0 = __ldg(&b2[n]);
            const float bn1 = __ldg(&b2[n + 1]);
            float2 o0 = make_float2(c[mt][nt][0] + bn0, c[mt][nt][1] + bn1);
            float2 o1 = make_float2(c[mt][nt][2] + bn0, c[mt][nt][3] + bn1);
            Ls[ml * 65 + n]           = o0.x;
            Ls[ml * 65 + n + 1]       = o0.y;
            Ls[(ml + 8) * 65 + n]     = o1.x;
            Ls[(ml + 8) * 65 + n + 1] = o1.y;
            *(float2*)&out_logits[(size_t)m * N_EXP + n]       = o0;
            *(float2*)&out_logits[(size_t)(m + 8) * N_EXP + n] = o1;
        }
    }
    __syncthreads();

    // top-2 + softmax (128 tokens, one thread each)
    if (tid < 128) {
        const float* row = &Ls[tid * 65];
        float v1 = -1e30f, v2 = -1e30f;
        int   i1 = 0,      i2 = 0;
        #pragma unroll 8
        for (int e = 0; e < N_EXP; e++) {
            float v = row[e];
            if (v > v1) { v2 = v1; i2 = i1; v1 = v; i1 = e; }
            else if (v > v2) { v2 = v; i2 = e; }
        }
        float e2  = expf(v2 - v1);
        float inv = 1.0f / (1.0f + e2);
        sg1[tid] = inv;
        sg2[tid] = e2 * inv;
        si1[tid] = i1;
        si2[tid] = i2;
    }
    __syncthreads();

    // dense gate scatter: token = tid>>1, experts (tid&1)*32 .. +31
    {
        const int t  = tid >> 1;
        const int eb = (tid & 1) * 32;
        const int i1 = si1[t], i2 = si2[t];
        const float g1 = sg1[t], g2 = sg2[t];
        float* orow = &out[(size_t)(m0 + t) * N_EXP + eb];
        #pragma unroll
        for (int j = 0; j < 8; j++) {
            float4 o;
            float v[4];
            #pragma unroll
            for (int q = 0; q < 4; q++) {
                const int e = eb + j * 4 + q;
                v[q] = (e == i1) ? g1 : ((e == i2) ? g2 : 0.0f);
            }
            o.x = v[0]; o.y = v[1]; o.z = v[2]; o.w = v[3];
            *(float4*)&orow[j * 4] = o;
        }
    }
}

// ---------------------------------------------------------------------------
extern "C" void kernel_launch(void* const* d_in, const int* in_sizes, int n_in,
                              void* d_out, int out_size) {
    const float* x  = (const float*)d_in[0];
    const float* W1 = (const float*)d_in[1];
    const float* b1 = (const float*)d_in[2];
    const float* W2 = (const float*)d_in[3];
    const float* b2 = (const float*)d_in[4];
    float* out = (float*)d_out;

    static int init = 0;
    if (!init) {
        cudaFuncSetAttribute(gemm1_mma,
                             cudaFuncAttributeMaxDynamicSharedMemorySize, G1_SMEM);
        cudaFuncSetAttribute(gemm2_mma,
                             cudaFuncAttributeMaxDynamicSharedMemorySize, G2_SMEM);
        init = 1;
    }

    prep_w<<<dim3(8, 32, 2), 256>>>(W1, W2);
    gemm1_mma<<<dim3(2, 128), 256, G1_SMEM>>>(x, b1);
    gemm2_mma<<<M_TOK / 128, 256, G2_SMEM>>>(b2, out);
}

// round 6
// speedup vs baseline: 2.3276x; 1.1889x over previous
#include <cuda_runtime.h>
#include <cuda_fp16.h>
#include <math.h>
#include <stdint.h>

#define M_TOK 16384
#define D_IN  1024
#define D_HID 256
#define N_EXP 64

// Packed hi/lo fp16 weight splits: uint2 = {half2(hi0,hi1), half2(lo0,lo1)}
__device__ uint2 g_w1p[D_HID * (D_IN / 2)];   // W1^T packed [256][512]
__device__ uint2 g_w2p[N_EXP * (D_HID / 2)];  // W2^T packed [64][128]

// ---------------------------------------------------------------------------
__device__ __forceinline__ uint32_t smem_u32(const void* p) {
    uint32_t a;
    asm("{ .reg .u64 t; cvta.to.shared.u64 t, %1; cvt.u32.u64 %0, t; }"
        : "=r"(a) : "l"(p));
    return a;
}
__device__ __forceinline__ void cp16(uint32_t dst, const void* src) {
    asm volatile("cp.async.cg.shared.global [%0], [%1], 16;"
                 :: "r"(dst), "l"(src));
}
__device__ __forceinline__ uint32_t pack_h2(float a, float b) {
    __half2 h = __floats2half2_rn(a, b);
    return *(uint32_t*)&h;
}
__device__ __forceinline__ uint2 split2(float v0, float v1) {
    float h0 = __half2float(__float2half_rn(v0));
    float h1 = __half2float(__float2half_rn(v1));
    uint2 u;
    u.x = pack_h2(h0, h1);
    u.y = pack_h2(v0 - h0, v1 - h1);
    return u;
}
__device__ __forceinline__ void mma_f16(float* c, uint32_t a0, uint32_t a1,
                                        uint32_t a2, uint32_t a3,
                                        uint32_t b0, uint32_t b1) {
    asm volatile(
        "mma.sync.aligned.m16n8k16.row.col.f32.f16.f16.f32 "
        "{%0,%1,%2,%3}, {%4,%5,%6,%7}, {%8,%9}, {%0,%1,%2,%3};"
        : "+f"(c[0]), "+f"(c[1]), "+f"(c[2]), "+f"(c[3])
        : "r"(a0), "r"(a1), "r"(a2), "r"(a3), "r"(b0), "r"(b1));
}

// ---------------------------------------------------------------------------
// Prep: transpose + fp16 hi/lo split + pack for W1 (z=0) and W2 (z=1)
// ---------------------------------------------------------------------------
__global__ void __launch_bounds__(256)
prep_w(const float* __restrict__ W1, const float* __restrict__ W2) {
    __shared__ float t[32][33];
    const int z = blockIdx.z;
    if (z == 1 && (blockIdx.x >= 2 || blockIdx.y >= 8)) return;

    const int n0 = blockIdx.x * 32;
    const int k0 = blockIdx.y * 32;
    const int tx = threadIdx.x & 31;
    const int ty = threadIdx.x >> 5;
    const float* W    = z ? W2 : W1;
    const int   ncols = z ? N_EXP : D_HID;

    #pragma unroll
    for (int i = 0; i < 32; i += 8)
        t[ty + i][tx] = W[(k0 + ty + i) * ncols + n0 + tx];
    __syncthreads();

    const int nn = threadIdx.x >> 3;
    const int jj = threadIdx.x & 7;
    uint2* dst = z ? g_w2p : g_w1p;
    const int kp_pitch = z ? (D_HID / 2) : (D_IN / 2);
    #pragma unroll
    for (int q = 0; q < 2; q++) {
        const int p = jj * 2 + q;
        dst[(size_t)(n0 + nn) * kp_pitch + k0 / 2 + p] =
            split2(t[2 * p][nn], t[2 * p + 1][nn]);
    }
}

// ---------------------------------------------------------------------------
// Fused: gemm1(fp16x3) -> tanh -> gemm2(fp16x3, A from registers) -> top2.
// Grid 128 CTAs x 256 thr (8 warps). Warp tile 32x128: wm=(w&3)*32, K-half
// warps wn = (w>>2)*128. gemm1 acc fragments == gemm2 A fragments.
//
// dynamic smem:
//  mainloop: A [0,20480)  B0 [20480,61440)  B1 [61440,102400)
//  phase2:   W2s [0,67584)  Ls1 [67584,+33280)  Ls2 [100864,+33280)
// ---------------------------------------------------------------------------
#define PITCH    20       // uint2 pitch, 16-kpair tiles
#define W2_PITCH 132      // uint2 pitch, 128-kpair W2 tile
#define SMEM_BYTES 134144

__global__ void __launch_bounds__(256)
fused_gate(const float* __restrict__ x, const float* __restrict__ b1,
           const float* __restrict__ b2, float* __restrict__ out) {
    extern __shared__ char smc[];
    uint2* const As = (uint2*)smc;
    uint2* const Bs[2] = {(uint2*)(smc + 20480), (uint2*)(smc + 61440)};
    __shared__ float sb2[64];
    __shared__ float sg1[128], sg2[128];
    __shared__ int   si1[128], si2[128];

    const int tid  = threadIdx.x;
    const int lane = tid & 31;
    const int grp  = lane >> 2;
    const int kq   = lane & 3;
    const int w    = tid >> 5;
    const int wm   = (w & 3) * 32;
    const int wn   = (w >> 2) * 128;       // gemm1 N-half == gemm2 K-half
    const int m0   = blockIdx.x * 128;

    const uint32_t uB[2] = {smem_u32(Bs[0]), smem_u32(Bs[1])};
    if (tid < 64) sb2[tid] = b2[tid];

    float c[2][16][4] = {};
    float4 xv[4];

    // ---- prologue
    #pragma unroll
    for (int r = 0; r < 8; r++) {
        int idx = tid + 256 * r;
        int row = idx >> 3, g = idx & 7;
        cp16(uB[0] + (uint32_t)(row * PITCH + g * 2) * 8,
             &g_w1p[(size_t)row * 512 + g * 2]);
    }
    asm volatile("cp.async.commit_group;" ::: "memory");
    #pragma unroll
    for (int r = 0; r < 4; r++) {
        int idx = tid + 256 * r;
        int row = idx >> 3, g = idx & 7;
        xv[r] = *(const float4*)&x[(size_t)(m0 + row) * D_IN + g * 4];
    }

    // ---- gemm1 mainloop: K=1024, KC=32
    for (int kb = 0; kb < D_IN / 32; kb++) {
        const int buf = kb & 1;

        #pragma unroll
        for (int r = 0; r < 4; r++) {
            int idx = tid + 256 * r;
            int row = idx >> 3, g = idx & 7;
            uint2 p0 = split2(xv[r].x, xv[r].y);
            uint2 p1 = split2(xv[r].z, xv[r].w);
            *(uint4*)&As[row * PITCH + g * 2] =
                make_uint4(p0.x, p0.y, p1.x, p1.y);
        }

        if (kb < D_IN / 32 - 1) {
            const int nk = (kb + 1) * 32;
            #pragma unroll
            for (int r = 0; r < 8; r++) {
                int idx = tid + 256 * r;
                int row = idx >> 3, g = idx & 7;
                cp16(uB[buf ^ 1] + (uint32_t)(row * PITCH + g * 2) * 8,
                     &g_w1p[(size_t)row * 512 + nk / 2 + g * 2]);
            }
            asm volatile("cp.async.commit_group;" ::: "memory");
            #pragma unroll
            for (int r = 0; r < 4; r++) {
                int idx = tid + 256 * r;
                int row = idx >> 3, g = idx & 7;
                xv[r] = *(const float4*)&x[(size_t)(m0 + row) * D_IN + nk + g * 4];
            }
            asm volatile("cp.async.wait_group 1;" ::: "memory");
        } else {
            asm volatile("cp.async.wait_group 0;" ::: "memory");
        }
        __syncthreads();

        const uint2* const cB = Bs[buf];
        #pragma unroll
        for (int s = 0; s < 2; s++) {
            const int kb8 = s * 8;
            uint2 Af[2][4];
            #pragma unroll
            for (int mt = 0; mt < 2; mt++) {
                const int mr = wm + mt * 16 + grp;
                Af[mt][0] = As[mr * PITCH + kb8 + kq];
                Af[mt][1] = As[(mr + 8) * PITCH + kb8 + kq];
                Af[mt][2] = As[mr * PITCH + kb8 + 4 + kq];
                Af[mt][3] = As[(mr + 8) * PITCH + kb8 + 4 + kq];
            }
            #pragma unroll
            for (int nt = 0; nt < 16; nt++) {
                const int n = wn + nt * 8 + grp;
                uint2 b0 = cB[n * PITCH + kb8 + kq];
                uint2 b1v = cB[n * PITCH + kb8 + 4 + kq];
                #pragma unroll
                for (int mt = 0; mt < 2; mt++) {
                    mma_f16(c[mt][nt], Af[mt][0].x, Af[mt][1].x,
                            Af[mt][2].x, Af[mt][3].x, b0.x, b1v.x);
                    mma_f16(c[mt][nt], Af[mt][0].x, Af[mt][1].x,
                            Af[mt][2].x, Af[mt][3].x, b0.y, b1v.y);
                    mma_f16(c[mt][nt], Af[mt][0].y, Af[mt][1].y,
                            Af[mt][2].y, Af[mt][3].y, b0.x, b1v.x);
                }
            }
        }
        __syncthreads();
    }

    // ---- load W2 tile into freed smem (overlap with tanh/split below)
    uint2* const W2s = (uint2*)smc;
    {
        const uint32_t uW2 = smem_u32(W2s);
        #pragma unroll
        for (int r = 0; r < 16; r++) {
            int idx = tid + 256 * r;             // 0..4095
            int n = idx >> 6, kpp = (idx & 63) * 2;
            cp16(uW2 + (uint32_t)(n * W2_PITCH + kpp) * 8,
                 &g_w2p[(size_t)n * 128 + kpp]);
        }
        asm volatile("cp.async.commit_group;" ::: "memory");
    }

    // ---- tanh + b1, re-split to fp16 hi/lo: gemm2 A-fragments in registers
    uint2 ph[2][16], pl[2][16];
    #pragma unroll
    for (int mt = 0; mt < 2; mt++) {
        #pragma unroll
        for (int nt = 0; nt < 16; nt++) {
            const int col = wn + nt * 8 + kq * 2;
            const float bc0 = __ldg(&b1[col]);
            const float bc1 = __ldg(&b1[col + 1]);
            float t0 = tanhf(c[mt][nt][0] + bc0);
            float t1 = tanhf(c[mt][nt][1] + bc1);
            float t2 = tanhf(c[mt][nt][2] + bc0);
            float t3 = tanhf(c[mt][nt][3] + bc1);
            ph[mt][nt] = split2(t0, t1);    // rows wm+16mt+grp
            pl[mt][nt] = split2(t2, t3);    // rows wm+16mt+grp+8
        }
    }
    asm volatile("cp.async.wait_group 0;" ::: "memory");
    __syncthreads();

    // ---- gemm2: logits partials over this warp's K-half (A from regs)
    const int kho = (w >> 2) * 64;          // kpair offset of K-half
    float c2[2][8][4] = {};
    #pragma unroll
    for (int s = 0; s < 8; s++) {
        #pragma unroll
        for (int ntB = 0; ntB < 8; ntB++) {
            const int n = 8 * ntB + grp;
            uint2 b0  = W2s[n * W2_PITCH + kho + 8 * s + kq];
            uint2 b1v = W2s[n * W2_PITCH + kho + 8 * s + 4 + kq];
            #pragma unroll
            for (int mt = 0; mt < 2; mt++) {
                uint2 A0 = ph[mt][2 * s], A1 = pl[mt][2 * s];
                uint2 A2 = ph[mt][2 * s + 1], A3 = pl[mt][2 * s + 1];
                mma_f16(c2[mt][ntB], A0.x, A1.x, A2.x, A3.x, b0.x, b1v.x);
                mma_f16(c2[mt][ntB], A0.x, A1.x, A2.x, A3.x, b0.y, b1v.y);
                mma_f16(c2[mt][ntB], A0.y, A1.y, A2.y, A3.y, b0.x, b1v.x);
            }
        }
    }

    // ---- write logit partials (two K-half buffers)
    float* const LsH = (float*)(smc + 67584 + (w >> 2) * 33280);
    #pragma unroll
    for (int mt = 0; mt < 2; mt++) {
        const int R0 = wm + mt * 16 + grp;
        #pragma unroll
        for (int ntB = 0; ntB < 8; ntB++) {
            const int e0 = ntB * 8 + kq * 2;
            LsH[R0 * 65 + e0]           = c2[mt][ntB][0];
            LsH[R0 * 65 + e0 + 1]       = c2[mt][ntB][1];
            LsH[(R0 + 8) * 65 + e0]     = c2[mt][ntB][2];
            LsH[(R0 + 8) * 65 + e0 + 1] = c2[mt][ntB][3];
        }
    }
    __syncthreads();

    float* const Ls1 = (float*)(smc + 67584);
    float* const Ls2 = (float*)(smc + 100864);

    // ---- top-2 + softmax (one thread per token)
    if (tid < 128) {
        float v1 = -1e30f, v2 = -1e30f;
        int   i1 = 0,      i2 = 0;
        #pragma unroll 8
        for (int e = 0; e < N_EXP; e++) {
            float v = Ls1[tid * 65 + e] + Ls2[tid * 65 + e] + sb2[e];
            if (v > v1) { v2 = v1; i2 = i1; v1 = v; i1 = e; }
            else if (v > v2) { v2 = v; i2 = e; }
        }
        float e2  = expf(v2 - v1);
        float inv = 1.0f / (1.0f + e2);
        sg1[tid] = inv;
        sg2[tid] = e2 * inv;
        si1[tid] = i1;
        si2[tid] = i2;
    }
    __syncthreads();

    // ---- write logits + gates (token = tid>>1, expert half = (tid&1)*32)
    {
        const int t  = tid >> 1;
        const int eb = (tid & 1) * 32;
        const int i1 = si1[t], i2 = si2[t];
        const float g1 = sg1[t], g2 = sg2[t];
        float* orow = &out[(size_t)(m0 + t) * N_EXP + eb];
        float* lrow = &out[(size_t)M_TOK * N_EXP + (size_t)(m0 + t) * N_EXP + eb];
        #pragma unroll
        for (int j = 0; j < 8; j++) {
            float4 lg, gt;
            float lv[4], gv[4];
            #pragma unroll
            for (int q = 0; q < 4; q++) {
                const int e = eb + j * 4 + q;
                lv[q] = Ls1[t * 65 + e] + Ls2[t * 65 + e] + sb2[e];
                gv[q] = (e == i1) ? g1 : ((e == i2) ? g2 : 0.0f);
            }
            lg.x = lv[0]; lg.y = lv[1]; lg.z = lv[2]; lg.w = lv[3];
            gt.x = gv[0]; gt.y = gv[1]; gt.z = gv[2]; gt.w = gv[3];
            *(float4*)&lrow[j * 4] = lg;
            *(float4*)&orow[j * 4] = gt;
        }
    }
}

// ---------------------------------------------------------------------------
extern "C" void kernel_launch(void* const* d_in, const int* in_sizes, int n_in,
                              void* d_out, int out_size) {
    const float* x  = (const float*)d_in[0];
    const float* W1 = (const float*)d_in[1];
    const float* b1 = (const float*)d_in[2];
    const float* W2 = (const float*)d_in[3];
    const float* b2 = (const float*)d_in[4];
    float* out = (float*)d_out;

    static int init = 0;
    if (!init) {
        cudaFuncSetAttribute(fused_gate,
                             cudaFuncAttributeMaxDynamicSharedMemorySize,
                             SMEM_BYTES);
        init = 1;
    }

    prep_w<<<dim3(8, 32, 2), 256>>>(W1, W2);
    fused_gate<<<M_TOK / 128, 256, SMEM_BYTES>>>(x, b1, b2, out);
}

// round 9
// speedup vs baseline: 2.7025x; 1.1611x over previous
#include <cuda_runtime.h>
#include <cuda_fp16.h>
#include <math.h>
#include <stdint.h>

#define M_TOK 16384
#define D_IN  1024
#define D_HID 256
#define N_EXP 64

// Packed hi/lo fp16 weight splits: uint2 = {half2(hi0,hi1), half2(lo0,lo1)}
__device__ uint2 g_w1p[D_HID * (D_IN / 2)];   // W1^T packed [256][512]
__device__ uint2 g_w2p[N_EXP * (D_HID / 2)];  // W2^T packed [64][128]

// ---------------------------------------------------------------------------
__device__ __forceinline__ uint32_t smem_u32(const void* p) {
    uint32_t a;
    asm("{ .reg .u64 t; cvta.to.shared.u64 t, %1; cvt.u32.u64 %0, t; }"
        : "=r"(a) : "l"(p));
    return a;
}
__device__ __forceinline__ void cp16(uint32_t dst, const void* src) {
    asm volatile("cp.async.cg.shared.global [%0], [%1], 16;"
                 :: "r"(dst), "l"(src));
}
__device__ __forceinline__ uint32_t pack_h2(float a, float b) {
    __half2 h = __floats2half2_rn(a, b);
    return *(uint32_t*)&h;
}
__device__ __forceinline__ uint2 split2(float v0, float v1) {
    float h0 = __half2float(__float2half_rn(v0));
    float h1 = __half2float(__float2half_rn(v1));
    uint2 u;
    u.x = pack_h2(h0, h1);
    u.y = pack_h2(v0 - h0, v1 - h1);
    return u;
}
__device__ __forceinline__ void mma_f16(float* c, uint32_t a0, uint32_t a1,
                                        uint32_t a2, uint32_t a3,
                                        uint32_t b0, uint32_t b1) {
    asm volatile(
        "mma.sync.aligned.m16n8k16.row.col.f32.f16.f16.f32 "
        "{%0,%1,%2,%3}, {%4,%5,%6,%7}, {%8,%9}, {%0,%1,%2,%3};"
        : "+f"(c[0]), "+f"(c[1]), "+f"(c[2]), "+f"(c[3])
        : "r"(a0), "r"(a1), "r"(a2), "r"(a3), "r"(b0), "r"(b1));
}

// ---------------------------------------------------------------------------
// Prep: transpose + fp16 hi/lo split + pack for W1 (z=0) and W2 (z=1)
// ---------------------------------------------------------------------------
__global__ void __launch_bounds__(256)
prep_w(const float* __restrict__ W1, const float* __restrict__ W2) {
    __shared__ float t[32][33];
    const int z = blockIdx.z;
    if (z == 1 && (blockIdx.x >= 2 || blockIdx.y >= 8)) return;

    const int n0 = blockIdx.x * 32;
    const int k0 = blockIdx.y * 32;
    const int tx = threadIdx.x & 31;
    const int ty = threadIdx.x >> 5;
    const float* W    = z ? W2 : W1;
    const int   ncols = z ? N_EXP : D_HID;

    #pragma unroll
    for (int i = 0; i < 32; i += 8)
        t[ty + i][tx] = W[(k0 + ty + i) * ncols + n0 + tx];
    __syncthreads();

    const int nn = threadIdx.x >> 3;
    const int jj = threadIdx.x & 7;
    uint2* dst = z ? g_w2p : g_w1p;
    const int kp_pitch = z ? (D_HID / 2) : (D_IN / 2);
    #pragma unroll
    for (int q = 0; q < 2; q++) {
        const int p = jj * 2 + q;
        dst[(size_t)(n0 + nn) * kp_pitch + k0 / 2 + p] =
            split2(t[2 * p][nn], t[2 * p + 1][nn]);
    }
}

// ---------------------------------------------------------------------------
// Fused: gemm1(fp16x3, A direct-from-gmem regs, B 3-stage cp.async ring)
//        -> tanh -> gemm2(fp16x3, A from registers) -> top2 -> scatter.
// Grid 128 CTAs x 256 thr (8 warps). Warp tile 32x128.
// smem mainloop: B stages 3 x 40960 = 122880
// smem phase2:   W2s [0,67584)  Ls1 [67584,+33280)  Ls2 [100864,+33280)
// ---------------------------------------------------------------------------
#define PITCH    20       // uint2 pitch for B stage rows
#define W2_PITCH 132
#define B_STAGE  40960
#define SMEM_BYTES 134144

__global__ void __launch_bounds__(256)
fused_gate(const float* __restrict__ x, const float* __restrict__ b1,
           const float* __restrict__ b2, float* __restrict__ out) {
    extern __shared__ char smc[];
    __shared__ float sb2[64];
    __shared__ float sg1[128], sg2[128];
    __shared__ int   si1[128], si2[128];

    const int tid  = threadIdx.x;
    const int lane = tid & 31;
    const int grp  = lane >> 2;
    const int kq   = lane & 3;
    const int w    = tid >> 5;
    const int wm   = (w & 3) * 32;
    const int wn   = (w >> 2) * 128;       // gemm1 N-half == gemm2 K-half
    const int m0   = blockIdx.x * 128;

    const uint32_t uB = smem_u32(smc);
    if (tid < 64) sb2[tid] = b2[tid];

    // B-stage fill: 8 cp16 per thread (2048 x 16B = full 256x16kpair tile)
    const int frow = tid >> 3;             // 0..31 base, +32 per r... (idx>>3)
    const int fg   = tid & 7;

#define FILL_B(stage, kb)                                                     \
    {                                                                         \
        const uint32_t dstb = uB + (stage) * B_STAGE;                         \
        _Pragma("unroll")                                                     \
        for (int r = 0; r < 8; r++) {                                         \
            int row = frow + r * 32;                                          \
            cp16(dstb + (uint32_t)(row * PITCH + fg * 2) * 8,                 \
                 &g_w1p[(size_t)row * 512 + (kb) * 16 + fg * 2]);             \
        }                                                                     \
        asm volatile("cp.async.commit_group;" ::: "memory");                  \
    }

    // x row pointers for this thread's A-fragment rows
    const float* xr[4];
    #pragma unroll
    for (int i = 0; i < 4; i++)
        xr[i] = x + (size_t)(m0 + wm + i * 8 + grp) * D_IN + kq * 2;

    float c[2][16][4] = {};
    float2 xv[16];
    uint2  fr[16];

    // prologue: B stages 0,1 + x(kb=0)
    FILL_B(0, 0);
    FILL_B(1, 1);
    #pragma unroll
    for (int s = 0; s < 2; s++)
        #pragma unroll
        for (int mt = 0; mt < 2; mt++)
            #pragma unroll
            for (int j = 0; j < 4; j++)
                xv[(s * 2 + mt) * 4 + j] =
                    *(const float2*)(xr[2 * mt + (j & 1)] + s * 16 + (j >> 1) * 8);

    int st = 0;                            // stage of current kb
    for (int kb = 0; kb < 32; kb++) {
        if (kb == 31) {
            asm volatile("cp.async.wait_group 0;" ::: "memory");
        } else {
            asm volatile("cp.async.wait_group 1;" ::: "memory");
        }
        __syncthreads();

        if (kb < 30) {
            int nst = st + 2; if (nst >= 3) nst -= 3;
            FILL_B(nst, kb + 2);
        }

        // split current x into fragments (frees xv)
        #pragma unroll
        for (int i = 0; i < 16; i++)
            fr[i] = split2(xv[i].x, xv[i].y);

        // prefetch next x
        if (kb < 31) {
            const int nk = (kb + 1) * 32;
            #pragma unroll
            for (int s = 0; s < 2; s++)
                #pragma unroll
                for (int mt = 0; mt < 2; mt++)
                    #pragma unroll
                    for (int j = 0; j < 4; j++)
                        xv[(s * 2 + mt) * 4 + j] =
                            *(const float2*)(xr[2 * mt + (j & 1)] + nk +
                                             s * 16 + (j >> 1) * 8);
        }

        const uint2* const cB = (const uint2*)(smc + st * B_STAGE);
        #pragma unroll
        for (int s = 0; s < 2; s++) {
            const int kp = s * 8 + kq;
            #pragma unroll
            for (int nt = 0; nt < 16; nt++) {
                const int n = wn + nt * 8 + grp;
                uint2 b0  = cB[n * PITCH + kp];
                uint2 b1v = cB[n * PITCH + kp + 4];
                #pragma unroll
                for (int mt = 0; mt < 2; mt++) {
                    const uint2* f = &fr[(s * 2 + mt) * 4];
                    mma_f16(c[mt][nt], f[0].x, f[1].x, f[2].x, f[3].x,
                            b0.x, b1v.x);                       // hi*hi
                    mma_f16(c[mt][nt], f[0].x, f[1].x, f[2].x, f[3].x,
                            b0.y, b1v.y);                       // hi*lo
                    mma_f16(c[mt][nt], f[0].y, f[1].y, f[2].y, f[3].y,
                            b0.x, b1v.x);                       // lo*hi
                }
            }
        }
        st++; if (st >= 3) st -= 3;
    }

    // ---- load W2 tile into smem [0,67584) (stages 0,1 region; safe: all
    // warps passed kb=31 top-barrier; kb=31 MMA reads stage 2 only)
    uint2* const W2s = (uint2*)smc;
    {
        #pragma unroll
        for (int r = 0; r < 16; r++) {
            int idx = tid + 256 * r;
            int n = idx >> 6, kpp = (idx & 63) * 2;
            cp16(uB + (uint32_t)(n * W2_PITCH + kpp) * 8,
                 &g_w2p[(size_t)n * 128 + kpp]);
        }
        asm volatile("cp.async.commit_group;" ::: "memory");
    }

    // ---- tanh + b1, re-split: gemm2 A-fragments in registers
    uint2 ph[2][16], pl[2][16];
    #pragma unroll
    for (int mt = 0; mt < 2; mt++) {
        #pragma unroll
        for (int nt = 0; nt < 16; nt++) {
            const int col = wn + nt * 8 + kq * 2;
            const float bc0 = __ldg(&b1[col]);
            const float bc1 = __ldg(&b1[col + 1]);
            float t0 = tanhf(c[mt][nt][0] + bc0);
            float t1 = tanhf(c[mt][nt][1] + bc1);
            float t2 = tanhf(c[mt][nt][2] + bc0);
            float t3 = tanhf(c[mt][nt][3] + bc1);
            ph[mt][nt] = split2(t0, t1);    // rows wm+16mt+grp
            pl[mt][nt] = split2(t2, t3);    // rows wm+16mt+grp+8
        }
    }
    asm volatile("cp.async.wait_group 0;" ::: "memory");
    __syncthreads();

    // ---- gemm2: logits partials over this warp's K-half (A from regs)
    const int kho = (w >> 2) * 64;
    float c2[2][8][4] = {};
    #pragma unroll
    for (int s = 0; s < 8; s++) {
        #pragma unroll
        for (int ntB = 0; ntB < 8; ntB++) {
            const int n = 8 * ntB + grp;
            uint2 b0  = W2s[n * W2_PITCH + kho + 8 * s + kq];
            uint2 b1v = W2s[n * W2_PITCH + kho + 8 * s + 4 + kq];
            #pragma unroll
            for (int mt = 0; mt < 2; mt++) {
                uint2 A0 = ph[mt][2 * s], A1 = pl[mt][2 * s];
                uint2 A2 = ph[mt][2 * s + 1], A3 = pl[mt][2 * s + 1];
                mma_f16(c2[mt][ntB], A0.x, A1.x, A2.x, A3.x, b0.x, b1v.x);
                mma_f16(c2[mt][ntB], A0.x, A1.x, A2.x, A3.x, b0.y, b1v.y);
                mma_f16(c2[mt][ntB], A0.y, A1.y, A2.y, A3.y, b0.x, b1v.x);
            }
        }
    }

    // ---- write logit partials (two K-half buffers)
    float* const LsH = (float*)(smc + 67584 + (w >> 2) * 33280);
    #pragma unroll
    for (int mt = 0; mt < 2; mt++) {
        const int R0 = wm + mt * 16 + grp;
        #pragma unroll
        for (int ntB = 0; ntB < 8; ntB++) {
            const int e0 = ntB * 8 + kq * 2;
            LsH[R0 * 65 + e0]           = c2[mt][ntB][0];
            LsH[R0 * 65 + e0 + 1]       = c2[mt][ntB][1];
            LsH[(R0 + 8) * 65 + e0]     = c2[mt][ntB][2];
            LsH[(R0 + 8) * 65 + e0 + 1] = c2[mt][ntB][3];
        }
    }
    __syncthreads();

    float* const Ls1 = (float*)(smc + 67584);
    float* const Ls2 = (float*)(smc + 100864);

    // ---- top-2 + softmax (one thread per token)
    if (tid < 128) {
        float v1 = -1e30f, v2 = -1e30f;
        int   i1 = 0,      i2 = 0;
        #pragma unroll 8
        for (int e = 0; e < N_EXP; e++) {
            float v = Ls1[tid * 65 + e] + Ls2[tid * 65 + e] + sb2[e];
            if (v > v1) { v2 = v1; i2 = i1; v1 = v; i1 = e; }
            else if (v > v2) { v2 = v; i2 = e; }
        }
        float e2  = expf(v2 - v1);
        float inv = 1.0f / (1.0f + e2);
        sg1[tid] = inv;
        sg2[tid] = e2 * inv;
        si1[tid] = i1;
        si2[tid] = i2;
    }
    __syncthreads();

    // ---- write logits + gates (token = tid>>1, expert half = (tid&1)*32)
    {
        const int t  = tid >> 1;
        const int eb = (tid & 1) * 32;
        const int i1 = si1[t], i2 = si2[t];
        const float g1 = sg1[t], g2 = sg2[t];
        float* orow = &out[(size_t)(m0 + t) * N_EXP + eb];
        float* lrow = &out[(size_t)M_TOK * N_EXP + (size_t)(m0 + t) * N_EXP + eb];
        #pragma unroll
        for (int j = 0; j < 8; j++) {
            float4 lg, gt;
            float lv[4], gv[4];
            #pragma unroll
            for (int q = 0; q < 4; q++) {
                const int e = eb + j * 4 + q;
                lv[q] = Ls1[t * 65 + e] + Ls2[t * 65 + e] + sb2[e];
                gv[q] = (e == i1) ? g1 : ((e == i2) ? g2 : 0.0f);
            }
            lg.x = lv[0]; lg.y = lv[1]; lg.z = lv[2]; lg.w = lv[3];
            gt.x = gv[0]; gt.y = gv[1]; gt.z = gv[2]; gt.w = gv[3];
            *(float4*)&lrow[j * 4] = lg;
            *(float4*)&orow[j * 4] = gt;
        }
    }
}

// ---------------------------------------------------------------------------
extern "C" void kernel_launch(void* const* d_in, const int* in_sizes, int n_in,
                              void* d_out, int out_size) {
    const float* x  = (const float*)d_in[0];
    const float* W1 = (const float*)d_in[1];
    const float* b1 = (const float*)d_in[2];
    const float* W2 = (const float*)d_in[3];
    const float* b2 = (const float*)d_in[4];
    float* out = (float*)d_out;

    static int init = 0;
    if (!init) {
        cudaFuncSetAttribute(fused_gate,
                             cudaFuncAttributeMaxDynamicSharedMemorySize,
                             SMEM_BYTES);
        init = 1;
    }

    prep_w<<<dim3(8, 32, 2), 256>>>(W1, W2);
    fused_gate<<<M_TOK / 128, 256, SMEM_BYTES>>>(x, b1, b2, out);
}

// round 10
// speedup vs baseline: 3.1352x; 1.1601x over previous
#include <cuda_runtime.h>
#include <cuda_fp16.h>
#include <math.h>
#include <stdint.h>

#define M_TOK 16384
#define D_IN  1024
#define D_HID 256
#define N_EXP 64

// Packed hi/lo fp16 weight splits, kpair-PERMUTED within each 8-kpair group:
// group inner order [0,4,1,5,2,6,3,7] so (q, q+4) sit adjacent -> LDS.128.
__device__ uint2 g_w1p[D_HID * (D_IN / 2)];   // W1^T packed [256][512]
__device__ uint2 g_w2p[N_EXP * (D_HID / 2)];  // W2^T packed [64][128]

// ---------------------------------------------------------------------------
__device__ __forceinline__ uint32_t smem_u32(const void* p) {
    uint32_t a;
    asm("{ .reg .u64 t; cvta.to.shared.u64 t, %1; cvt.u32.u64 %0, t; }"
        : "=r"(a) : "l"(p));
    return a;
}
__device__ __forceinline__ void cp16(uint32_t dst, const void* src) {
    asm volatile("cp.async.cg.shared.global [%0], [%1], 16;"
                 :: "r"(dst), "l"(src));
}
__device__ __forceinline__ uint32_t pack_h2(float a, float b) {
    __half2 h = __floats2half2_rn(a, b);
    return *(uint32_t*)&h;
}
__device__ __forceinline__ uint2 split2(float v0, float v1) {
    float h0 = __half2float(__float2half_rn(v0));
    float h1 = __half2float(__float2half_rn(v1));
    uint2 u;
    u.x = pack_h2(h0, h1);
    u.y = pack_h2(v0 - h0, v1 - h1);
    return u;
}
__device__ __forceinline__ void mma_f16(float* c, uint32_t a0, uint32_t a1,
                                        uint32_t a2, uint32_t a3,
                                        uint32_t b0, uint32_t b1) {
    asm volatile(
        "mma.sync.aligned.m16n8k16.row.col.f32.f16.f16.f32 "
        "{%0,%1,%2,%3}, {%4,%5,%6,%7}, {%8,%9}, {%0,%1,%2,%3};"
        : "+f"(c[0]), "+f"(c[1]), "+f"(c[2]), "+f"(c[3])
        : "r"(a0), "r"(a1), "r"(a2), "r"(a3), "r"(b0), "r"(b1));
}

// ---------------------------------------------------------------------------
// Prep: transpose + fp16 hi/lo split + pack (permuted kpair order)
// ---------------------------------------------------------------------------
__global__ void __launch_bounds__(256)
prep_w(const float* __restrict__ W1, const float* __restrict__ W2) {
    __shared__ float t[32][33];
    const int z = blockIdx.z;
    if (z == 1 && (blockIdx.x >= 2 || blockIdx.y >= 8)) return;

    const int n0 = blockIdx.x * 32;
    const int k0 = blockIdx.y * 32;
    const int tx = threadIdx.x & 31;
    const int ty = threadIdx.x >> 5;
    const float* W    = z ? W2 : W1;
    const int   ncols = z ? N_EXP : D_HID;

    #pragma unroll
    for (int i = 0; i < 32; i += 8)
        t[ty + i][tx] = W[(k0 + ty + i) * ncols + n0 + tx];
    __syncthreads();

    const int nn = threadIdx.x >> 3;
    const int jj = threadIdx.x & 7;
    uint2* dst = z ? g_w2p : g_w1p;
    const int kp_pitch = z ? (D_HID / 2) : (D_IN / 2);
    #pragma unroll
    for (int q = 0; q < 2; q++) {
        const int p     = jj * 2 + q;                 // local kpair 0..15
        const int inner = p & 7;
        const int pos   = (p & 8) | ((inner & 3) * 2) | (inner >> 2);
        dst[(size_t)(n0 + nn) * kp_pitch + k0 / 2 + pos] =
            split2(t[2 * p][nn], t[2 * p + 1][nn]);
    }
}

// ---------------------------------------------------------------------------
// Fused kernel. Grid 128 CTAs x 256 thr (8 warps). Warp tile 32x128.
// Mainloop: B 3-stage cp.async ring (stage 49152 B, PITCH 24), A from gmem
// regs, split2 moved off the barrier->MMA critical path.
// Phase2: W2s [0,69632)  Ls1 [69632,+33280)  Ls2 [102912,+33280)
// ---------------------------------------------------------------------------
#define PITCH    24
#define W2_PITCH 136
#define B_STAGE  49152
#define SMEM_BYTES 147456

__global__ void __launch_bounds__(256)
fused_gate(const float* __restrict__ x, const float* __restrict__ b1,
           const float* __restrict__ b2, float* __restrict__ out) {
    extern __shared__ char smc[];
    __shared__ float sb2[64];
    __shared__ float sg1[128], sg2[128];
    __shared__ int   si1[128], si2[128];

    const int tid  = threadIdx.x;
    const int lane = tid & 31;
    const int grp  = lane >> 2;
    const int kq   = lane & 3;
    const int w    = tid >> 5;
    const int wm   = (w & 3) * 32;
    const int wn   = (w >> 2) * 128;       // gemm1 N-half == gemm2 K-half
    const int m0   = blockIdx.x * 128;

    const uint32_t uB = smem_u32(smc);
    if (tid < 64) sb2[tid] = b2[tid];

    const int frow = tid >> 3;
    const int fg   = tid & 7;

#define FILL_B(stage, kb)                                                     \
    {                                                                         \
        const uint32_t dstb = uB + (stage) * B_STAGE;                         \
        _Pragma("unroll")                                                     \
        for (int r = 0; r < 8; r++) {                                         \
            int row = frow + r * 32;                                          \
            cp16(dstb + (uint32_t)(row * PITCH + fg * 2) * 8,                 \
                 &g_w1p[(size_t)row * 512 + (kb) * 16 + fg * 2]);             \
        }                                                                     \
        asm volatile("cp.async.commit_group;" ::: "memory");                  \
    }

    // x row pointers for this thread's A-fragment rows
    const float* xr[4];
    #pragma unroll
    for (int i = 0; i < 4; i++)
        xr[i] = x + (size_t)(m0 + wm + i * 8 + grp) * D_IN + kq * 2;

#define LOAD_X(kb)                                                            \
    {                                                                         \
        const int nk = (kb) * 32;                                             \
        _Pragma("unroll")                                                     \
        for (int s = 0; s < 2; s++)                                           \
            _Pragma("unroll")                                                 \
            for (int mt = 0; mt < 2; mt++)                                    \
                _Pragma("unroll")                                             \
                for (int j = 0; j < 4; j++)                                   \
                    xv[(s * 2 + mt) * 4 + j] =                                \
                        *(const float2*)(xr[2 * mt + (j & 1)] + nk +          \
                                         s * 16 + (j >> 1) * 8);              \
    }

#define SPLIT_X(FRN)                                                          \
    {                                                                         \
        _Pragma("unroll")                                                     \
        for (int i = 0; i < 16; i++) FRN[i] = split2(xv[i].x, xv[i].y);       \
    }

#define MMA_SEC(FRC)                                                          \
    {                                                                         \
        const uint2* const cB = (const uint2*)(smc + st * B_STAGE);           \
        _Pragma("unroll")                                                     \
        for (int s = 0; s < 2; s++) {                                         \
            _Pragma("unroll")                                                 \
            for (int nt = 0; nt < 16; nt++) {                                 \
                const int n = wn + nt * 8 + grp;                              \
                uint4 bv = *(const uint4*)&cB[n * PITCH + s * 8 + 2 * kq];    \
                _Pragma("unroll")                                             \
                for (int mt = 0; mt < 2; mt++) {                              \
                    const uint2* f = &FRC[(s * 2 + mt) * 4];                  \
                    mma_f16(c[mt][nt], f[0].x, f[1].x, f[2].x, f[3].x,        \
                            bv.x, bv.z);                                      \
                    mma_f16(c[mt][nt], f[0].x, f[1].x, f[2].x, f[3].x,        \
                            bv.y, bv.w);                                      \
                    mma_f16(c[mt][nt], f[0].y, f[1].y, f[2].y, f[3].y,        \
                            bv.x, bv.z);                                      \
                }                                                             \
            }                                                                 \
        }                                                                     \
    }

#define STEP(kb, FRC, FRN, WAITN, DOFILL, DOPREF)                             \
    {                                                                         \
        asm volatile("cp.async.wait_group " #WAITN ";" ::: "memory");         \
        __syncthreads();                                                      \
        if (DOFILL) { int nst = (st < 1) ? 2 : st - 1; FILL_B(nst, (kb) + 2); } \
        if (DOPREF) LOAD_X((kb) + 1);                                         \
        MMA_SEC(FRC);                                                         \
        if (DOPREF) SPLIT_X(FRN);                                             \
        st = (st + 1 < 3) ? st + 1 : 0;                                       \
    }

    float c[2][16][4] = {};
    float2 xv[16];
    uint2  fr0[16], fr1[16];

    // prologue
    FILL_B(0, 0);
    FILL_B(1, 1);
    LOAD_X(0);
    SPLIT_X(fr0);

    int st = 0;
    #pragma unroll 1
    for (int kb2 = 0; kb2 < 15; kb2++) {
        const int kb = 2 * kb2;
        STEP(kb,     fr0, fr1, 1, 1, 1);
        STEP(kb + 1, fr1, fr0, 1, 1, 1);
    }
    STEP(30, fr0, fr1, 1, 0, 1);
    STEP(31, fr1, fr0, 0, 0, 0);

    // mainloop fully done (all warps) before W2 fill reuses B-stage smem
    __syncthreads();

    // ---- load W2 tile into smem [0,69632)
    uint2* const W2s = (uint2*)smc;
    {
        #pragma unroll
        for (int r = 0; r < 16; r++) {
            int idx = tid + 256 * r;
            int n = idx >> 6, kpp = (idx & 63) * 2;
            cp16(uB + (uint32_t)(n * W2_PITCH + kpp) * 8,
                 &g_w2p[(size_t)n * 128 + kpp]);
        }
        asm volatile("cp.async.commit_group;" ::: "memory");
    }

    // ---- tanh + b1, re-split: gemm2 A-fragments in registers
    uint2 ph[2][16], pl[2][16];
    #pragma unroll
    for (int mt = 0; mt < 2; mt++) {
        #pragma unroll
        for (int nt = 0; nt < 16; nt++) {
            const int col = wn + nt * 8 + kq * 2;
            const float bc0 = __ldg(&b1[col]);
            const float bc1 = __ldg(&b1[col + 1]);
            float t0 = tanhf(c[mt][nt][0] + bc0);
            float t1 = tanhf(c[mt][nt][1] + bc1);
            float t2 = tanhf(c[mt][nt][2] + bc0);
            float t3 = tanhf(c[mt][nt][3] + bc1);
            ph[mt][nt] = split2(t0, t1);    // rows wm+16mt+grp
            pl[mt][nt] = split2(t2, t3);    // rows wm+16mt+grp+8
        }
    }
    asm volatile("cp.async.wait_group 0;" ::: "memory");
    __syncthreads();

    // ---- gemm2: logits partials over this warp's K-half (A from regs)
    const int kho = (w >> 2) * 64;
    float c2[2][8][4] = {};
    #pragma unroll
    for (int s = 0; s < 8; s++) {
        #pragma unroll
        for (int ntB = 0; ntB < 8; ntB++) {
            const int n = 8 * ntB + grp;
            uint4 bv = *(const uint4*)&W2s[n * W2_PITCH + kho + 8 * s + 2 * kq];
            #pragma unroll
            for (int mt = 0; mt < 2; mt++) {
                uint2 A0 = ph[mt][2 * s], A1 = pl[mt][2 * s];
                uint2 A2 = ph[mt][2 * s + 1], A3 = pl[mt][2 * s + 1];
                mma_f16(c2[mt][ntB], A0.x, A1.x, A2.x, A3.x, bv.x, bv.z);
                mma_f16(c2[mt][ntB], A0.x, A1.x, A2.x, A3.x, bv.y, bv.w);
                mma_f16(c2[mt][ntB], A0.y, A1.y, A2.y, A3.y, bv.x, bv.z);
            }
        }
    }

    // ---- write logit partials (two K-half buffers)
    float* const LsH = (float*)(smc + 69632 + (w >> 2) * 33280);
    #pragma unroll
    for (int mt = 0; mt < 2; mt++) {
        const int R0 = wm + mt * 16 + grp;
        #pragma unroll
        for (int ntB = 0; ntB < 8; ntB++) {
            const int e0 = ntB * 8 + kq * 2;
            LsH[R0 * 65 + e0]           = c2[mt][ntB][0];
            LsH[R0 * 65 + e0 + 1]       = c2[mt][ntB][1];
            LsH[(R0 + 8) * 65 + e0]     = c2[mt][ntB][2];
            LsH[(R0 + 8) * 65 + e0 + 1] = c2[mt][ntB][3];
        }
    }
    __syncthreads();

    float* const Ls1 = (float*)(smc + 69632);
    float* const Ls2 = (float*)(smc + 102912);

    // ---- top-2 + softmax (one thread per token)
    if (tid < 128) {
        float v1 = -1e30f, v2 = -1e30f;
        int   i1 = 0,      i2 = 0;
        #pragma unroll 8
        for (int e = 0; e < N_EXP; e++) {
            float v = Ls1[tid * 65 + e] + Ls2[tid * 65 + e] + sb2[e];
            if (v > v1) { v2 = v1; i2 = i1; v1 = v; i1 = e; }
            else if (v > v2) { v2 = v; i2 = e; }
        }
        float e2  = expf(v2 - v1);
        float inv = 1.0f / (1.0f + e2);
        sg1[tid] = inv;
        sg2[tid] = e2 * inv;
        si1[tid] = i1;
        si2[tid] = i2;
    }
    __syncthreads();

    // ---- write logits + gates (token = tid>>1, expert half = (tid&1)*32)
    {
        const int t  = tid >> 1;
        const int eb = (tid & 1) * 32;
        const int i1 = si1[t], i2 = si2[t];
        const float g1 = sg1[t], g2 = sg2[t];
        float* orow = &out[(size_t)(m0 + t) * N_EXP + eb];
        float* lrow = &out[(size_t)M_TOK * N_EXP + (size_t)(m0 + t) * N_EXP + eb];
        #pragma unroll
        for (int j = 0; j < 8; j++) {
            float4 lg, gt;
            float lv[4], gv[4];
            #pragma unroll
            for (int q = 0; q < 4; q++) {
                const int e = eb + j * 4 + q;
                lv[q] = Ls1[t * 65 + e] + Ls2[t * 65 + e] + sb2[e];
                gv[q] = (e == i1) ? g1 : ((e == i2) ? g2 : 0.0f);
            }
            lg.x = lv[0]; lg.y = lv[1]; lg.z = lv[2]; lg.w = lv[3];
            gt.x = gv[0]; gt.y = gv[1]; gt.z = gv[2]; gt.w = gv[3];
            *(float4*)&lrow[j * 4] = lg;
            *(float4*)&orow[j * 4] = gt;
        }
    }
}

// ---------------------------------------------------------------------------
extern "C" void kernel_launch(void* const* d_in, const int* in_sizes, int n_in,
                              void* d_out, int out_size) {
    const float* x  = (const float*)d_in[0];
    const float* W1 = (const float*)d_in[1];
    const float* b1 = (const float*)d_in[2];
    const float* W2 = (const float*)d_in[3];
    const float* b2 = (const float*)d_in[4];
    float* out = (float*)d_out;

    static int init = 0;
    if (!init) {
        cudaFuncSetAttribute(fused_gate,
                             cudaFuncAttributeMaxDynamicSharedMemorySize,
                             SMEM_BYTES);
        init = 1;
    }

    prep_w<<<dim3(8, 32, 2), 256>>>(W1, W2);
    fused_gate<<<M_TOK / 128, 256, SMEM_BYTES>>>(x, b1, b2, out);
}